// round 10
// baseline (speedup 1.0000x reference)
#include <cuda_runtime.h>
#include <cstdint>

namespace {
constexpr int B = 512, T = 512, D = 128, DOUT = 32, C = 4;
constexpr int NCB = 4;      // chunks over T (k_gemm)
constexpr int CTB = 128;    // timesteps per k_gemm block
constexpr int SUB = 32;     // timesteps per sub-tile
constexpr int NSUB = CTB / SUB;
constexpr float ALPHA  = 0.1f;
constexpr float GAMMA  = 0.9f;
constexpr float EPS    = 1e-5f;
constexpr float EPS_H  = 1e-6f;
constexpr float LN_EPS = 1e-5f;
constexpr float NLN_G  = 0.10536051565782628f;   // -ln(0.9)

constexpr int ZROW = 132;   // ps row pitch (floats)
constexpr int TROW = 36;    // zsT row pitch (floats)

// k_gemm smem layout (floats)
constexpr int OFF_PS   = 0;                    // [SUB][ZROW]: v-tile, then psum
constexpr int OFF_ZT   = OFF_PS + SUB * ZROW;  // [D][TROW]: delta2 -> z_tilde (transposed)
constexpr int OFF_VBAR = OFF_ZT + D * TROW;    // [32]
constexpr int OFF_IT   = OFF_VBAR + 32;        // [CTB] 1/tau
constexpr int OFF_IT1  = OFF_IT + CTB;         // [CTB] 1/max(tau-1,1)
constexpr int GSMEM_FLOATS = OFF_IT1 + CTB;
constexpr int GSMEM_BYTES  = GSMEM_FLOATS * 4; // ~36.5 KB
}

// scratch (static device globals — no allocation)
__device__ float g_s1[B * NCB * D];
__device__ float g_s2[B * NCB * D];
__device__ float g_r2[(size_t)B * T * DOUT];   // r^2 handoff (32 MB)

__device__ __forceinline__ void fma2(unsigned long long& d,
                                     unsigned long long a,
                                     unsigned long long b,
                                     unsigned long long c)
{
    asm("fma.rn.f32x2 %0, %1, %2, %3;" : "=l"(d) : "l"(a), "l"(b), "l"(c));
}
__device__ __forceinline__ unsigned long long splat2(float a) {
    unsigned long long r;
    asm("mov.b64 %0, {%1, %1};" : "=l"(r) : "f"(a));
    return r;
}

// ---------------------------------------------------------------------------
// K1: per-(b,chunk) sums of z, z^2 (Welford carry)
// ---------------------------------------------------------------------------
__global__ __launch_bounds__(128)
void k_stats(const float* __restrict__ z)
{
    const int b = blockIdx.x, c = blockIdx.y, d = threadIdx.x;
    const float* zp = z + ((size_t)(b * T + c * CTB)) * D + d;
    float s1 = 0.f, s2 = 0.f;
#pragma unroll 4
    for (int t = 0; t < CTB; ++t) {
        float zz = zp[(size_t)t * D];
        s1 += zz;
        s2 = fmaf(zz, zz, s2);
    }
    g_s1[(b * NCB + c) * D + d] = s1;
    g_s2[(b * NCB + c) * D + d] = s2;
}

// ---------------------------------------------------------------------------
// K2: normalize + project -> r^2 (global); block per (b, 128-t chunk)
// ---------------------------------------------------------------------------
__global__ __launch_bounds__(128, 6)
void k_gemm(const float* __restrict__ z, const float* __restrict__ proj)
{
    const int b = blockIdx.x, c = blockIdx.y;
    const int tid = threadIdx.x, lane = tid & 31, w = tid >> 5;

    extern __shared__ float sm[];
    float* ps   = sm + OFF_PS;     // v in phase1/1b, psum in phase2
    float* zsT  = sm + OFF_ZT;     // [d][t], pitch TROW
    float* vbar = sm + OFF_VBAR;
    float* itab = sm + OFF_IT;
    float* itab1= sm + OFF_IT1;

    const int t0 = c * CTB;
    {
        const float tau = (float)(t0 + tid + 1);
        itab[tid]  = 1.0f / tau;
        itab1[tid] = 1.0f / fmaxf(tau - 1.f, 1.f);
    }

    // Welford carry-in from chunk sums
    float s1 = 0.f, s2 = 0.f;
    for (int cp = 0; cp < c; ++cp) {
        s1 += g_s1[(b * NCB + cp) * D + tid];
        s2 += g_s2[(b * NCB + cp) * D + tid];
    }
    const float* zp = z + ((size_t)(b * T + t0)) * D + tid;

    const int tq2 = tid >> 2, jq2 = tid & 3;     // phase1b / 2b mapping
    const int jq = lane >> 3, tq = lane & 7;     // phase2 mapping
    __syncthreads();

    for (int sub = 0; sub < NSUB; ++sub) {
        // ---- phase1: Welford (thread = d) -> zsT[d][t] transposed, v -> ps ----
#pragma unroll 2
        for (int tg = 0; tg < SUB / 4; ++tg) {
            float4 d2q;
            float* d2a = (float*)&d2q;
#pragma unroll
            for (int i = 0; i < 4; ++i) {
                const int tl = tg * 4 + i;
                const int tb = sub * SUB + tl;
                const float zz = zp[(size_t)tb * D];
                s1 += zz;
                s2 = fmaf(zz, zz, s2);
                const float m = s1 * itab[tb];
                d2a[i] = zz - m;
                ps[tl * ZROW + tid] = fmaf(-s1, m, s2) * itab1[tb];
            }
            *(float4*)(zsT + tid * TROW + tg * 4) = d2q;
        }
        __syncthreads();

        // ---- phase1b: vbar per t (4 threads per t) ----
        {
            float p = 0.f;
            const float4* vr = (const float4*)(ps + tq2 * ZROW + jq2 * 32);
#pragma unroll
            for (int i = 0; i < 8; ++i) {
                const float4 q4 = vr[i];
                p += (q4.x + q4.y) + (q4.z + q4.w);
            }
            p += __shfl_xor_sync(0xffffffffu, p, 1);
            p += __shfl_xor_sync(0xffffffffu, p, 2);
            if (jq2 == 0) vbar[tq2] = p * (1.f / 128.f);
        }
        __syncthreads();

        // ---- phase1c: scale zsT row in place (thread = d) ----
#pragma unroll 2
        for (int i = 0; i < 8; ++i) {
            float4 q = *(const float4*)(zsT + tid * TROW + i * 4);
            float* qa = (float*)&q;
#pragma unroll
            for (int k = 0; k < 4; ++k) {
                const int tl = i * 4 + k;
                const float vt = fmaf(ALPHA, vbar[tl],
                                      (1.f - ALPHA) * ps[tl * ZROW + tid]);
                qa[k] *= rsqrtf(vt + EPS);
            }
            *(float4*)(zsT + tid * TROW + i * 4) = q;
        }
        __syncthreads();

        // ---- phase2: GEMM microkernel; proj read from global (L1-hot) ----
        // warp w: d in [32w,32w+32); thread (jq,tq): 8 j x 4 t tile.
        {
            unsigned long long acc[4][4];
#pragma unroll
            for (int i = 0; i < 4; ++i)
#pragma unroll
                for (int jj = 0; jj < 4; ++jj) acc[i][jj] = 0ull;

            const float* ztw = zsT + (w * 32) * TROW + tq * 4;
            const float* ppw = proj + (w * 32) * DOUT + jq * 8;
#pragma unroll 4
            for (int d = 0; d < 32; ++d) {
                const float4 zq = *(const float4*)(ztw + d * TROW);
                const ulonglong2 pa = *(const ulonglong2*)(ppw + d * DOUT);
                const unsigned long long z0 = splat2(zq.x), z1 = splat2(zq.y);
                const unsigned long long z2 = splat2(zq.z), z3 = splat2(zq.w);
                fma2(acc[0][0], z0, pa.x, acc[0][0]);
                fma2(acc[0][1], z0, pa.y, acc[0][1]);
                fma2(acc[1][0], z1, pa.x, acc[1][0]);
                fma2(acc[1][1], z1, pa.y, acc[1][1]);
                fma2(acc[2][0], z2, pa.x, acc[2][0]);
                fma2(acc[2][1], z2, pa.y, acc[2][1]);
                fma2(acc[3][0], z3, pa.x, acc[3][0]);
                fma2(acc[3][1], z3, pa.y, acc[3][1]);
                const ulonglong2 pb = *(const ulonglong2*)(ppw + d * DOUT + 4);
                fma2(acc[0][2], z0, pb.x, acc[0][2]);
                fma2(acc[0][3], z0, pb.y, acc[0][3]);
                fma2(acc[1][2], z1, pb.x, acc[1][2]);
                fma2(acc[1][3], z1, pb.y, acc[1][3]);
                fma2(acc[2][2], z2, pb.x, acc[2][2]);
                fma2(acc[2][3], z2, pb.y, acc[2][3]);
                fma2(acc[3][2], z3, pb.x, acc[3][2]);
                fma2(acc[3][3], z3, pb.y, acc[3][3]);
            }
#pragma unroll
            for (int i = 0; i < 4; ++i) {
                ulonglong2* dst = (ulonglong2*)(ps + (tq * 4 + i) * ZROW + w * 32 + jq * 8);
                dst[0] = make_ulonglong2(acc[i][0], acc[i][1]);
                dst[1] = make_ulonglong2(acc[i][2], acc[i][3]);
            }
        }
        __syncthreads();

        // ---- phase2b: reduce 4 warp partials -> r^2 -> GLOBAL ----
        {
            const int j0 = jq2 * 8;
            float rl[8];
#pragma unroll
            for (int i = 0; i < 8; ++i) rl[i] = 0.f;
#pragma unroll
            for (int ws = 0; ws < 4; ++ws) {
                const float4* p4 = (const float4*)(ps + tq2 * ZROW + ws * 32 + j0);
                const float4 q0 = p4[0], q1 = p4[1];
                rl[0] += q0.x; rl[1] += q0.y; rl[2] += q0.z; rl[3] += q0.w;
                rl[4] += q1.x; rl[5] += q1.y; rl[6] += q1.z; rl[7] += q1.w;
            }
            float4* ro = (float4*)(g_r2 + ((size_t)(b * T + t0 + sub * SUB + tq2)) * DOUT + j0);
            ro[0] = make_float4(rl[0]*rl[0], rl[1]*rl[1], rl[2]*rl[2], rl[3]*rl[3]);
            ro[1] = make_float4(rl[4]*rl[4], rl[5]*rl[5], rl[6]*rl[6], rl[7]*rl[7]);
        }
        __syncthreads();
    }
}

// ---------------------------------------------------------------------------
// K3: full-T gamma-prefix + log + LayerNorm + classifier; block = b, thread = t
// ---------------------------------------------------------------------------
__global__ __launch_bounds__(512, 2)
void k_tail(const float* __restrict__ ln_w, const float* __restrict__ ln_b,
            const float* __restrict__ cls_w, const float* __restrict__ cls_b,
            float* __restrict__ x_out, float* __restrict__ logits_out)
{
    const int b = blockIdx.x;
    const int t = threadIdx.x;          // 0..511
    const int lane = t & 31, w = t >> 5; // 16 warps

    __shared__ float wtot[16][DOUT];
    __shared__ float lnw[32], lnb[32], cw[4][32], cb[4];

    if (t < 32) { lnw[t] = ln_w[t]; lnb[t] = ln_b[t]; }
    if (t >= 32 && t < 160) cw[(t - 32) >> 5][(t - 32) & 31] = cls_w[t - 32];
    if (t >= 160 && t < 164) cb[t - 160] = cls_b[t - 160];

    // load r^2 row, scale by gamma^{-t}
    float a[32];
    {
        const float4* rr = (const float4*)(g_r2 + ((size_t)(b * T + t)) * DOUT);
        const float gu = __expf((float)t * NLN_G);   // gamma^{-t}
#pragma unroll
        for (int i = 0; i < 8; ++i) {
            const float4 q4 = rr[i];
            a[4 * i]     = q4.x * gu; a[4 * i + 1] = q4.y * gu;
            a[4 * i + 2] = q4.z * gu; a[4 * i + 3] = q4.w * gu;
        }
    }

    // intra-warp inclusive prefix (per j) in gamma^{-t} space
#pragma unroll
    for (int j = 0; j < 32; ++j) {
        float v = a[j];
#pragma unroll
        for (int o = 1; o < 32; o <<= 1) {
            const float n = __shfl_up_sync(0xffffffffu, v, o);
            if (lane >= o) v += n;
        }
        a[j] = v;
    }
    if (lane == 31) {
        float4* wt = (float4*)wtot[w];
#pragma unroll
        for (int i = 0; i < 8; ++i)
            wt[i] = make_float4(a[4 * i], a[4 * i + 1], a[4 * i + 2], a[4 * i + 3]);
    }
    __syncthreads();

    // warp 0: exclusive prefix over 16 warp totals (thread = j)
    if (w == 0) {
        float run = 0.f;
#pragma unroll
        for (int wp = 0; wp < 16; ++wp) {
            const float tmp = wtot[wp][lane];
            wtot[wp][lane] = run;
            run += tmp;
        }
    }
    __syncthreads();

    // add carry
    {
        const float4* wt = (const float4*)wtot[w];
#pragma unroll
        for (int i = 0; i < 8; ++i) {
            const float4 q4 = wt[i];
            a[4 * i] += q4.x; a[4 * i + 1] += q4.y;
            a[4 * i + 2] += q4.z; a[4 * i + 3] += q4.w;
        }
    }

    const float gl = __expf(-(float)t * NLN_G);     // gamma^{t}
    const float sden = (1.f - __expf(-(float)(t + 1) * NLN_G)) * (1.f / (1.f - GAMMA));
    const float sinv = __fdividef(1.f, sden);

    // x = log(h/s + eps_h), h = gamma^t * prefix
#pragma unroll
    for (int j = 0; j < 32; ++j)
        a[j] = __logf(fmaf(a[j] * gl, sinv, EPS_H));

    // LayerNorm (thread-local over 32 j)
    float mu = 0.f;
#pragma unroll
    for (int j = 0; j < 32; ++j) mu += a[j];
    mu *= (1.f / 32.f);
    float var = 0.f;
#pragma unroll
    for (int j = 0; j < 32; ++j) { const float dd = a[j] - mu; var = fmaf(dd, dd, var); }
    var *= (1.f / 32.f);
    const float rs = rsqrtf(var + LN_EPS);

    float l0 = 0.f, l1 = 0.f, l2 = 0.f, l3 = 0.f;
#pragma unroll
    for (int j = 0; j < 32; ++j) {
        const float xn = fmaf((a[j] - mu) * rs, lnw[j], lnb[j]);
        l0 = fmaf(xn, cw[0][j], l0);
        l1 = fmaf(xn, cw[1][j], l1);
        l2 = fmaf(xn, cw[2][j], l2);
        l3 = fmaf(xn, cw[3][j], l3);
    }

    float4* xo = (float4*)(x_out + ((size_t)(b * T + t)) * DOUT);
#pragma unroll
    for (int i = 0; i < 8; ++i)
        xo[i] = make_float4(a[4 * i], a[4 * i + 1], a[4 * i + 2], a[4 * i + 3]);
    float4* lo = (float4*)(logits_out + ((size_t)(b * T + t)) * C);
    lo[0] = make_float4(l0 + cb[0], l1 + cb[1], l2 + cb[2], l3 + cb[3]);
}

// ---------------------------------------------------------------------------
extern "C" void kernel_launch(void* const* d_in, const int* in_sizes, int n_in,
                              void* d_out, int out_size)
{
    const float* z     = (const float*)d_in[0];
    const float* proj  = (const float*)d_in[1];
    const float* ln_w  = (const float*)d_in[2];
    const float* ln_b  = (const float*)d_in[3];
    const float* cls_w = (const float*)d_in[4];
    const float* cls_b = (const float*)d_in[5];

    float* out        = (float*)d_out;
    float* x_out      = out;
    float* logits_out = out + (size_t)B * T * DOUT;

    cudaFuncSetAttribute(k_gemm, cudaFuncAttributeMaxDynamicSharedMemorySize,
                         GSMEM_BYTES);

    k_stats<<<dim3(B, NCB), 128>>>(z);
    k_gemm<<<dim3(B, NCB), 128, GSMEM_BYTES>>>(z, proj);
    k_tail<<<B, 512>>>(ln_w, ln_b, cls_w, cls_b, x_out, logits_out);
}

// round 11
// speedup vs baseline: 1.6848x; 1.6848x over previous
#include <cuda_runtime.h>
#include <cstdint>

namespace {
constexpr int B = 512, T = 512, D = 128, DOUT = 32, C = 4;
constexpr int NCB = 4;      // chunks over T
constexpr int CTB = 128;    // timesteps per block
constexpr int SUB = 32;     // timesteps per sub-tile
constexpr int NSUB = CTB / SUB;
constexpr float ALPHA  = 0.1f;
constexpr float GAMMA  = 0.9f;
constexpr float EPS    = 1e-5f;
constexpr float EPS_H  = 1e-6f;
constexpr float LN_EPS = 1e-5f;
constexpr float NLN_G  = 0.10536051565782628f;   // -ln(0.9)

constexpr int ZROW = 132;   // ps row pitch (floats)
constexpr int TROW = 36;    // zsT row pitch (floats)

// k_gemm smem layout (floats)
constexpr int OFF_PS   = 0;                    // [SUB][ZROW]: v-tile, then psum
constexpr int OFF_ZT   = OFF_PS + SUB * ZROW;  // [D][TROW]: delta2 -> z_tilde (transposed)
constexpr int OFF_P    = OFF_ZT + D * TROW;    // [D][DOUT]: proj
constexpr int OFF_VBAR = OFF_P + D * DOUT;     // [32]
constexpr int OFF_IT   = OFF_VBAR + 32;        // [CTB] 1/tau
constexpr int OFF_IT1  = OFF_IT + CTB;         // [CTB] 1/max(tau-1,1)
constexpr int GSMEM_FLOATS = OFF_IT1 + CTB;
constexpr int GSMEM_BYTES  = GSMEM_FLOATS * 4; // ~52.9 KB
}

// scratch (static device globals — no allocation)
__device__ float g_s1[B * NCB * D];
__device__ float g_s2[B * NCB * D];
__device__ float g_r2[(size_t)B * T * DOUT];   // r^2 handoff (32 MB)
__device__ float g_hfull[B * NCB * DOUT];      // h at chunk end (lookback)
__device__ int   g_flag[B * NCB];

__device__ __forceinline__ void fma2(unsigned long long& d,
                                     unsigned long long a,
                                     unsigned long long b,
                                     unsigned long long c)
{
    asm("fma.rn.f32x2 %0, %1, %2, %3;" : "=l"(d) : "l"(a), "l"(b), "l"(c));
}
__device__ __forceinline__ unsigned long long splat2(float a) {
    unsigned long long r;
    asm("mov.b64 %0, {%1, %1};" : "=l"(r) : "f"(a));
    return r;
}

// ---------------------------------------------------------------------------
// K1: per-(b,chunk) sums of z, z^2 (Welford carry) + flag reset
// ---------------------------------------------------------------------------
__global__ __launch_bounds__(128)
void k_stats(const float* __restrict__ z)
{
    const int b = blockIdx.x, c = blockIdx.y, d = threadIdx.x;
    const float* zp = z + ((size_t)(b * T + c * CTB)) * D + d;
    float s1a = 0.f, s2a = 0.f, s1b = 0.f, s2b = 0.f;
#pragma unroll 4
    for (int t = 0; t < CTB; t += 2) {
        const float z0 = zp[(size_t)t * D];
        const float z1 = zp[(size_t)(t + 1) * D];
        s1a += z0; s2a = fmaf(z0, z0, s2a);
        s1b += z1; s2b = fmaf(z1, z1, s2b);
    }
    g_s1[(b * NCB + c) * D + d] = s1a + s1b;
    g_s2[(b * NCB + c) * D + d] = s2a + s2b;
    if (d == 0) g_flag[b * NCB + c] = 0;
}

// ---------------------------------------------------------------------------
// K2: normalize + project -> r^2 (global); block per (b, 128-t chunk)
// ---------------------------------------------------------------------------
__global__ __launch_bounds__(128, 4)
void k_gemm(const float* __restrict__ z, const float* __restrict__ proj)
{
    const int b = blockIdx.x, c = blockIdx.y;
    const int tid = threadIdx.x, lane = tid & 31, w = tid >> 5;

    extern __shared__ float sm[];
    float* ps   = sm + OFF_PS;     // v in phase1/1b, psum in phase2
    float* zsT  = sm + OFF_ZT;     // [d][t], pitch TROW
    float* Psm  = sm + OFF_P;      // proj [d][j], pitch 32
    float* vbar = sm + OFF_VBAR;
    float* itab = sm + OFF_IT;
    float* itab1= sm + OFF_IT1;

    const int t0 = c * CTB;

#pragma unroll
    for (int i = 0; i < D * DOUT / 128; ++i)
        Psm[i * 128 + tid] = proj[i * 128 + tid];
    {
        const float tau = (float)(t0 + tid + 1);
        itab[tid]  = 1.0f / tau;
        itab1[tid] = 1.0f / fmaxf(tau - 1.f, 1.f);
    }

    // Welford carry-in from chunk sums
    float s1 = 0.f, s2 = 0.f;
    for (int cp = 0; cp < c; ++cp) {
        s1 += g_s1[(b * NCB + cp) * D + tid];
        s2 += g_s2[(b * NCB + cp) * D + tid];
    }
    const float* zp = z + ((size_t)(b * T + t0)) * D + tid;

    const int tq2 = tid >> 2, jq2 = tid & 3;     // phase1b / 2b mapping
    const int jq = lane >> 3, tq = lane & 7;     // phase2 mapping
    __syncthreads();

    for (int sub = 0; sub < NSUB; ++sub) {
        // ---- phase1: Welford (thread = d) -> zsT[d][t] transposed, v -> ps ----
#pragma unroll 2
        for (int tg = 0; tg < SUB / 4; ++tg) {
            float4 d2q;
            float* d2a = (float*)&d2q;
#pragma unroll
            for (int i = 0; i < 4; ++i) {
                const int tl = tg * 4 + i;
                const int tb = sub * SUB + tl;
                const float zz = zp[(size_t)tb * D];
                s1 += zz;
                s2 = fmaf(zz, zz, s2);
                const float m = s1 * itab[tb];
                d2a[i] = zz - m;
                ps[tl * ZROW + tid] = fmaf(-s1, m, s2) * itab1[tb];
            }
            *(float4*)(zsT + tid * TROW + tg * 4) = d2q;
        }
        __syncthreads();

        // ---- phase1b: vbar per t (4 threads per t) ----
        {
            float p = 0.f;
            const float4* vr = (const float4*)(ps + tq2 * ZROW + jq2 * 32);
#pragma unroll
            for (int i = 0; i < 8; ++i) {
                const float4 q4 = vr[i];
                p += (q4.x + q4.y) + (q4.z + q4.w);
            }
            p += __shfl_xor_sync(0xffffffffu, p, 1);
            p += __shfl_xor_sync(0xffffffffu, p, 2);
            if (jq2 == 0) vbar[tq2] = p * (1.f / 128.f);
        }
        __syncthreads();

        // ---- phase1c: scale zsT row in place (thread = d) ----
#pragma unroll 2
        for (int i = 0; i < 8; ++i) {
            float4 q = *(const float4*)(zsT + tid * TROW + i * 4);
            float* qa = (float*)&q;
#pragma unroll
            for (int k = 0; k < 4; ++k) {
                const int tl = i * 4 + k;
                const float vt = fmaf(ALPHA, vbar[tl],
                                      (1.f - ALPHA) * ps[tl * ZROW + tid]);
                qa[k] *= rsqrtf(vt + EPS);
            }
            *(float4*)(zsT + tid * TROW + i * 4) = q;
        }
        __syncthreads();

        // ---- phase2: GEMM microkernel from smem (proven R9 path) ----
        // warp w: d in [32w,32w+32); thread (jq,tq): 8 j x 4 t tile.
        {
            unsigned long long acc[4][4];
#pragma unroll
            for (int i = 0; i < 4; ++i)
#pragma unroll
                for (int jj = 0; jj < 4; ++jj) acc[i][jj] = 0ull;

            const float* ztw = zsT + (w * 32) * TROW + tq * 4;
            const float* ppw = Psm + (w * 32) * DOUT + jq * 8;
#pragma unroll 4
            for (int d = 0; d < 32; ++d) {
                const float4 zq = *(const float4*)(ztw + d * TROW);
                const ulonglong2 pa = *(const ulonglong2*)(ppw + d * DOUT);
                const unsigned long long z0 = splat2(zq.x), z1 = splat2(zq.y);
                const unsigned long long z2 = splat2(zq.z), z3 = splat2(zq.w);
                fma2(acc[0][0], z0, pa.x, acc[0][0]);
                fma2(acc[0][1], z0, pa.y, acc[0][1]);
                fma2(acc[1][0], z1, pa.x, acc[1][0]);
                fma2(acc[1][1], z1, pa.y, acc[1][1]);
                fma2(acc[2][0], z2, pa.x, acc[2][0]);
                fma2(acc[2][1], z2, pa.y, acc[2][1]);
                fma2(acc[3][0], z3, pa.x, acc[3][0]);
                fma2(acc[3][1], z3, pa.y, acc[3][1]);
                const ulonglong2 pb = *(const ulonglong2*)(ppw + d * DOUT + 4);
                fma2(acc[0][2], z0, pb.x, acc[0][2]);
                fma2(acc[0][3], z0, pb.y, acc[0][3]);
                fma2(acc[1][2], z1, pb.x, acc[1][2]);
                fma2(acc[1][3], z1, pb.y, acc[1][3]);
                fma2(acc[2][2], z2, pb.x, acc[2][2]);
                fma2(acc[2][3], z2, pb.y, acc[2][3]);
                fma2(acc[3][2], z3, pb.x, acc[3][2]);
                fma2(acc[3][3], z3, pb.y, acc[3][3]);
            }
#pragma unroll
            for (int i = 0; i < 4; ++i) {
                ulonglong2* dst = (ulonglong2*)(ps + (tq * 4 + i) * ZROW + w * 32 + jq * 8);
                dst[0] = make_ulonglong2(acc[i][0], acc[i][1]);
                dst[1] = make_ulonglong2(acc[i][2], acc[i][3]);
            }
        }
        __syncthreads();

        // ---- phase2b: reduce 4 warp partials -> r^2 -> GLOBAL (write-only) ----
        {
            const int j0 = jq2 * 8;
            float rl[8];
#pragma unroll
            for (int i = 0; i < 8; ++i) rl[i] = 0.f;
#pragma unroll
            for (int ws = 0; ws < 4; ++ws) {
                const float4* p4 = (const float4*)(ps + tq2 * ZROW + ws * 32 + j0);
                const float4 q0 = p4[0], q1 = p4[1];
                rl[0] += q0.x; rl[1] += q0.y; rl[2] += q0.z; rl[3] += q0.w;
                rl[4] += q1.x; rl[5] += q1.y; rl[6] += q1.z; rl[7] += q1.w;
            }
            float4* ro = (float4*)(g_r2 + ((size_t)(b * T + t0 + sub * SUB + tq2)) * DOUT + j0);
            ro[0] = make_float4(rl[0]*rl[0], rl[1]*rl[1], rl[2]*rl[2], rl[3]*rl[3]);
            ro[1] = make_float4(rl[4]*rl[4], rl[5]*rl[5], rl[6]*rl[6], rl[7]*rl[7]);
        }
        __syncthreads();
    }
}

// ---------------------------------------------------------------------------
// K3: R9's phase3 as its own kernel — 128 threads, thread = local t,
// warp prefix + decoupled lookback across chunks.
// ---------------------------------------------------------------------------
__global__ __launch_bounds__(128)
void k_tail(const float* __restrict__ ln_w, const float* __restrict__ ln_b,
            const float* __restrict__ cls_w, const float* __restrict__ cls_b,
            float* __restrict__ x_out, float* __restrict__ logits_out)
{
    const int b = blockIdx.x, c = blockIdx.y;
    const int tid = threadIdx.x, lane = tid & 31, w = tid >> 5;
    const int t0 = c * CTB;

    __shared__ float wtot[4][DOUT];
    __shared__ float hps[DOUT];
    __shared__ float lnw[32], lnb[32], cw[128], cb[4];

    if (tid < 32) { lnw[tid] = ln_w[tid]; lnb[tid] = ln_b[tid]; }
    cw[tid] = cls_w[tid];
    if (tid < 4) cb[tid] = cls_b[tid];

    const int lt = tid;
    const int tg = t0 + lt;

    // load r^2 row, scale by gamma^{-lt}
    float a[32];
    {
        const float4* rr = (const float4*)(g_r2 + ((size_t)(b * T + tg)) * DOUT);
        const float gu = __expf((float)lt * NLN_G);   // gamma^{-lt}
#pragma unroll
        for (int i = 0; i < 8; ++i) {
            const float4 q4 = rr[i];
            a[4 * i]     = q4.x * gu; a[4 * i + 1] = q4.y * gu;
            a[4 * i + 2] = q4.z * gu; a[4 * i + 3] = q4.w * gu;
        }
    }

    // intra-warp inclusive prefix (per j)
#pragma unroll
    for (int j = 0; j < 32; ++j) {
        float v = a[j];
#pragma unroll
        for (int o = 1; o < 32; o <<= 1) {
            const float n = __shfl_up_sync(0xffffffffu, v, o);
            if (lane >= o) v += n;
        }
        a[j] = v;
    }
    if (lane == 31) {
        float4* wt = (float4*)wtot[w];
#pragma unroll
        for (int i = 0; i < 8; ++i)
            wt[i] = make_float4(a[4 * i], a[4 * i + 1], a[4 * i + 2], a[4 * i + 3]);
    }
    // decoupled lookback for previous chunk's h (c = slow grid index)
    if (c > 0 && tid == 0) {
        volatile int* f = (volatile int*)&g_flag[b * NCB + c - 1];
        while (*f == 0) { __nanosleep(40); }
    }
    __syncthreads();
    if (tid < 32)
        hps[tid] = (c > 0) ? g_hfull[(b * NCB + c - 1) * DOUT + tid] : 0.f;
    __syncthreads();

    // cross-warp prefix carry
#pragma unroll
    for (int wp = 0; wp < 3; ++wp) {
        if (w > wp) {
            const float4* wt = (const float4*)wtot[wp];
#pragma unroll
            for (int i = 0; i < 8; ++i) {
                const float4 q4 = wt[i];
                a[4 * i] += q4.x; a[4 * i + 1] += q4.y;
                a[4 * i + 2] += q4.z; a[4 * i + 3] += q4.w;
            }
        }
    }

    const float gl  = __expf(-(float)lt * NLN_G);   // gamma^{lt}
    const float gl1 = gl * GAMMA;                   // gamma^{lt+1}
    const float sden = (1.f - __expf(-(float)(tg + 1) * NLN_G)) * (1.f / (1.f - GAMMA));
    const float sinv = __fdividef(1.f, sden);

#pragma unroll
    for (int j = 0; j < 32; ++j)
        a[j] = fmaf(gl, a[j], gl1 * hps[j]);        // full h_t[j]

    if (tid == 127) {
        float4* hout = (float4*)&g_hfull[(b * NCB + c) * DOUT];
#pragma unroll
        for (int i = 0; i < 8; ++i)
            hout[i] = make_float4(a[4 * i], a[4 * i + 1], a[4 * i + 2], a[4 * i + 3]);
        __threadfence();
        atomicExch(&g_flag[b * NCB + c], 1);
    }

    // x = log(h/s + eps_h)
#pragma unroll
    for (int j = 0; j < 32; ++j)
        a[j] = __logf(fmaf(a[j], sinv, EPS_H));

    // LayerNorm (thread-local over 32 j)
    float mu = 0.f;
#pragma unroll
    for (int j = 0; j < 32; ++j) mu += a[j];
    mu *= (1.f / 32.f);
    float var = 0.f;
#pragma unroll
    for (int j = 0; j < 32; ++j) { const float dd = a[j] - mu; var = fmaf(dd, dd, var); }
    var *= (1.f / 32.f);
    const float rs = rsqrtf(var + LN_EPS);

    float l0 = 0.f, l1 = 0.f, l2 = 0.f, l3 = 0.f;
#pragma unroll
    for (int j = 0; j < 32; ++j) {
        const float xn = fmaf((a[j] - mu) * rs, lnw[j], lnb[j]);
        l0 = fmaf(xn, cw[j], l0);
        l1 = fmaf(xn, cw[32 + j], l1);
        l2 = fmaf(xn, cw[64 + j], l2);
        l3 = fmaf(xn, cw[96 + j], l3);
    }

    float4* xo = (float4*)(x_out + ((size_t)(b * T + tg)) * DOUT);
#pragma unroll
    for (int i = 0; i < 8; ++i)
        xo[i] = make_float4(a[4 * i], a[4 * i + 1], a[4 * i + 2], a[4 * i + 3]);
    float4* lo = (float4*)(logits_out + ((size_t)(b * T + tg)) * C);
    lo[0] = make_float4(l0 + cb[0], l1 + cb[1], l2 + cb[2], l3 + cb[3]);
}

// ---------------------------------------------------------------------------
extern "C" void kernel_launch(void* const* d_in, const int* in_sizes, int n_in,
                              void* d_out, int out_size)
{
    const float* z     = (const float*)d_in[0];
    const float* proj  = (const float*)d_in[1];
    const float* ln_w  = (const float*)d_in[2];
    const float* ln_b  = (const float*)d_in[3];
    const float* cls_w = (const float*)d_in[4];
    const float* cls_b = (const float*)d_in[5];

    float* out        = (float*)d_out;
    float* x_out      = out;
    float* logits_out = out + (size_t)B * T * DOUT;

    cudaFuncSetAttribute(k_gemm, cudaFuncAttributeMaxDynamicSharedMemorySize,
                         GSMEM_BYTES);

    k_stats<<<dim3(B, NCB), 128>>>(z);
    k_gemm<<<dim3(B, NCB), 128, GSMEM_BYTES>>>(z, proj);
    k_tail<<<dim3(B, NCB), 128>>>(ln_w, ln_b, cls_w, cls_b, x_out, logits_out);
}

// round 12
// speedup vs baseline: 1.7259x; 1.0244x over previous
#include <cuda_runtime.h>
#include <cstdint>

namespace {
constexpr int B = 512, T = 512, D = 128, DOUT = 32, C = 4;
constexpr int NCB = 4;      // chunks over T
constexpr int CTB = 128;    // timesteps per block
constexpr int SUB = 32;     // timesteps per sub-tile
constexpr int NSUB = CTB / SUB;
constexpr float ALPHA  = 0.1f;
constexpr float GAMMA  = 0.9f;
constexpr float EPS    = 1e-5f;
constexpr float EPS_H  = 1e-6f;
constexpr float LN_EPS = 1e-5f;
constexpr float NLN_G  = 0.10536051565782628f;   // -ln(0.9)

constexpr int ZROW = 132;   // ps row pitch (floats)
constexpr int TROW = 36;    // zsT / r2 row pitch (floats)

// smem layout (floats)  — identical to R9
constexpr int OFF_PS   = 0;                    // [SUB][ZROW]: v-tile, then psum
constexpr int OFF_ZT   = OFF_PS + SUB * ZROW;  // [D][TROW]: delta2 -> z_tilde (transposed)
constexpr int OFF_P    = OFF_ZT + D * TROW;    // [D][DOUT]: proj
constexpr int OFF_R2   = OFF_P + D * DOUT;     // [CTB][TROW]: r^2
constexpr int OFF_VBAR = OFF_R2 + CTB * TROW;  // [32]
constexpr int OFF_WTOT = OFF_VBAR + 32;        // [4][32]
constexpr int OFF_HP   = OFF_WTOT + 128;       // [32]
constexpr int OFF_LNW  = OFF_HP + 32;          // [32]
constexpr int OFF_LNB  = OFF_LNW + 32;         // [32]
constexpr int OFF_CW   = OFF_LNB + 32;         // [4][32]
constexpr int OFF_CB   = OFF_CW + 128;         // [4]
constexpr int OFF_IT   = OFF_CB + 4;           // [CTB] 1/tau
constexpr int OFF_IT1  = OFF_IT + CTB;         // [CTB] 1/max(tau-1,1)
constexpr int SMEM_FLOATS = OFF_IT1 + CTB;
constexpr int SMEM_BYTES  = SMEM_FLOATS * 4;   // ~73 KB -> 3 CTAs/SM
}

// scratch (static device globals — no allocation)
__device__ float g_s1[B * NCB * D];
__device__ float g_s2[B * NCB * D];
__device__ float g_hfull[B * NCB * DOUT];
__device__ int   g_flag[B * NCB];

__device__ __forceinline__ void fma2(unsigned long long& d,
                                     unsigned long long a,
                                     unsigned long long b,
                                     unsigned long long c)
{
    asm("fma.rn.f32x2 %0, %1, %2, %3;" : "=l"(d) : "l"(a), "l"(b), "l"(c));
}
__device__ __forceinline__ unsigned long long splat2(float a) {
    unsigned long long r;
    asm("mov.b64 %0, {%1, %1};" : "=l"(r) : "f"(a));
    return r;
}

// ---------------------------------------------------------------------------
// K1: per-(b,chunk) sums of z, z^2 (Welford carry) + flag reset
// ---------------------------------------------------------------------------
__global__ __launch_bounds__(128)
void k_stats(const float* __restrict__ z)
{
    const int b = blockIdx.x, c = blockIdx.y, d = threadIdx.x;
    const float* zp = z + ((size_t)(b * T + c * CTB)) * D + d;
    float s1a = 0.f, s2a = 0.f, s1b = 0.f, s2b = 0.f;
    float s1c = 0.f, s2c = 0.f, s1d = 0.f, s2d = 0.f;
#pragma unroll 2
    for (int t = 0; t < CTB; t += 4) {
        const float z0 = zp[(size_t)t * D];
        const float z1 = zp[(size_t)(t + 1) * D];
        const float z2 = zp[(size_t)(t + 2) * D];
        const float z3 = zp[(size_t)(t + 3) * D];
        s1a += z0; s2a = fmaf(z0, z0, s2a);
        s1b += z1; s2b = fmaf(z1, z1, s2b);
        s1c += z2; s2c = fmaf(z2, z2, s2c);
        s1d += z3; s2d = fmaf(z3, z3, s2d);
    }
    g_s1[(b * NCB + c) * D + d] = (s1a + s1b) + (s1c + s1d);
    g_s2[(b * NCB + c) * D + d] = (s2a + s2b) + (s2c + s2d);
    if (d == 0) g_flag[b * NCB + c] = 0;
}

// ---------------------------------------------------------------------------
// K2: fused normalize + project + h-prefix + tail; block per (b, 128-t chunk)
// R9 structure + register prefetch of next sub-tile's z.
// ---------------------------------------------------------------------------
__global__ __launch_bounds__(128)
void k_fused(const float* __restrict__ z, const float* __restrict__ proj,
             const float* __restrict__ ln_w, const float* __restrict__ ln_b,
             const float* __restrict__ cls_w, const float* __restrict__ cls_b,
             float* __restrict__ x_out, float* __restrict__ logits_out)
{
    const int b = blockIdx.x, c = blockIdx.y;
    const int tid = threadIdx.x, lane = tid & 31, w = tid >> 5;

    extern __shared__ float sm[];
    float* ps   = sm + OFF_PS;     // v-tile in phase1/1b/1c, psum in phase2
    float* zsT  = sm + OFF_ZT;     // [d][t], pitch TROW
    float* Psm  = sm + OFF_P;      // proj [d][j], pitch 32
    float* r2   = sm + OFF_R2;
    float* vbar = sm + OFF_VBAR;
    float* wtot = sm + OFF_WTOT;
    float* hps  = sm + OFF_HP;
    float* lnw  = sm + OFF_LNW;
    float* lnb  = sm + OFF_LNB;
    float* cw   = sm + OFF_CW;
    float* cb   = sm + OFF_CB;
    float* itab = sm + OFF_IT;
    float* itab1= sm + OFF_IT1;

    const int t0 = c * CTB;
    const float* zp = z + ((size_t)(b * T + t0)) * D + tid;

    // ---- prefetch sub 0's z into registers ----
    float zn[SUB];
#pragma unroll
    for (int i = 0; i < SUB; ++i)
        zn[i] = zp[(size_t)i * D];

    // ---- params + tables + proj into smem ----
#pragma unroll
    for (int i = 0; i < D * DOUT / 128; ++i)
        Psm[i * 128 + tid] = proj[i * 128 + tid];
    if (tid < 32) { lnw[tid] = ln_w[tid]; lnb[tid] = ln_b[tid]; }
    cw[tid] = cls_w[tid];
    if (tid < 4) cb[tid] = cls_b[tid];
    {
        const float tau = (float)(t0 + tid + 1);
        itab[tid]  = 1.0f / tau;
        itab1[tid] = 1.0f / fmaxf(tau - 1.f, 1.f);
    }

    // ---- Welford carry-in from chunk sums ----
    float s1 = 0.f, s2 = 0.f;
    for (int cp = 0; cp < c; ++cp) {
        s1 += g_s1[(b * NCB + cp) * D + tid];
        s2 += g_s2[(b * NCB + cp) * D + tid];
    }

    const int tq2 = tid >> 2, jq2 = tid & 3;     // phase1b / 2b mapping
    const int jq = lane >> 3, tq = lane & 7;     // phase2 mapping
    __syncthreads();

    for (int sub = 0; sub < NSUB; ++sub) {
        // ---- phase1: Welford from registers -> zsT transposed, v -> ps ----
#pragma unroll 2
        for (int tg = 0; tg < SUB / 4; ++tg) {
            float4 d2q;
            float* d2a = (float*)&d2q;
#pragma unroll
            for (int i = 0; i < 4; ++i) {
                const int tl = tg * 4 + i;
                const int tb = sub * SUB + tl;
                const float zz = zn[tl];
                s1 += zz;
                s2 = fmaf(zz, zz, s2);
                const float m = s1 * itab[tb];
                d2a[i] = zz - m;
                ps[tl * ZROW + tid] = fmaf(-s1, m, s2) * itab1[tb];
            }
            *(float4*)(zsT + tid * TROW + tg * 4) = d2q;
        }

        // ---- prefetch next sub's z (overlaps phase1b/1c/2) ----
        if (sub + 1 < NSUB) {
#pragma unroll
            for (int i = 0; i < SUB; ++i)
                zn[i] = zp[(size_t)((sub + 1) * SUB + i) * D];
        }
        __syncthreads();

        // ---- phase1b: vbar per t (4 threads per t) ----
        {
            float p = 0.f;
            const float4* vr = (const float4*)(ps + tq2 * ZROW + jq2 * 32);
#pragma unroll
            for (int i = 0; i < 8; ++i) {
                const float4 q4 = vr[i];
                p += (q4.x + q4.y) + (q4.z + q4.w);
            }
            p += __shfl_xor_sync(0xffffffffu, p, 1);
            p += __shfl_xor_sync(0xffffffffu, p, 2);
            if (jq2 == 0) vbar[tq2] = p * (1.f / 128.f);
        }
        __syncthreads();

        // ---- phase1c: scale zsT row in place (thread = d) ----
#pragma unroll 2
        for (int i = 0; i < 8; ++i) {
            float4 q = *(const float4*)(zsT + tid * TROW + i * 4);
            float* qa = (float*)&q;
#pragma unroll
            for (int k = 0; k < 4; ++k) {
                const int tl = i * 4 + k;
                const float vt = fmaf(ALPHA, vbar[tl],
                                      (1.f - ALPHA) * ps[tl * ZROW + tid]);
                qa[k] *= rsqrtf(vt + EPS);
            }
            *(float4*)(zsT + tid * TROW + i * 4) = q;
        }
        __syncthreads();

        // ---- phase2: GEMM microkernel from smem ----
        // warp w: d in [32w,32w+32); thread (jq,tq): 8 j x 4 t tile.
        {
            unsigned long long acc[4][4];
#pragma unroll
            for (int i = 0; i < 4; ++i)
#pragma unroll
                for (int jj = 0; jj < 4; ++jj) acc[i][jj] = 0ull;

            const float* ztw = zsT + (w * 32) * TROW + tq * 4;
            const float* ppw = Psm + (w * 32) * DOUT + jq * 8;
#pragma unroll 4
            for (int d = 0; d < 32; ++d) {
                const float4 zq = *(const float4*)(ztw + d * TROW);
                const ulonglong2 pa = *(const ulonglong2*)(ppw + d * DOUT);
                const unsigned long long z0 = splat2(zq.x), z1 = splat2(zq.y);
                const unsigned long long z2 = splat2(zq.z), z3 = splat2(zq.w);
                fma2(acc[0][0], z0, pa.x, acc[0][0]);
                fma2(acc[0][1], z0, pa.y, acc[0][1]);
                fma2(acc[1][0], z1, pa.x, acc[1][0]);
                fma2(acc[1][1], z1, pa.y, acc[1][1]);
                fma2(acc[2][0], z2, pa.x, acc[2][0]);
                fma2(acc[2][1], z2, pa.y, acc[2][1]);
                fma2(acc[3][0], z3, pa.x, acc[3][0]);
                fma2(acc[3][1], z3, pa.y, acc[3][1]);
                const ulonglong2 pb = *(const ulonglong2*)(ppw + d * DOUT + 4);
                fma2(acc[0][2], z0, pb.x, acc[0][2]);
                fma2(acc[0][3], z0, pb.y, acc[0][3]);
                fma2(acc[1][2], z1, pb.x, acc[1][2]);
                fma2(acc[1][3], z1, pb.y, acc[1][3]);
                fma2(acc[2][2], z2, pb.x, acc[2][2]);
                fma2(acc[2][3], z2, pb.y, acc[2][3]);
                fma2(acc[3][2], z3, pb.x, acc[3][2]);
                fma2(acc[3][3], z3, pb.y, acc[3][3]);
            }
#pragma unroll
            for (int i = 0; i < 4; ++i) {
                ulonglong2* dst = (ulonglong2*)(ps + (tq * 4 + i) * ZROW + w * 32 + jq * 8);
                dst[0] = make_ulonglong2(acc[i][0], acc[i][1]);
                dst[1] = make_ulonglong2(acc[i][2], acc[i][3]);
            }
        }
        __syncthreads();

        // ---- phase2b: reduce 4 warp partials -> r^2 (smem) ----
        {
            const int j0 = jq2 * 8;
            float rl[8];
#pragma unroll
            for (int i = 0; i < 8; ++i) rl[i] = 0.f;
#pragma unroll
            for (int ws = 0; ws < 4; ++ws) {
                const float4* p4 = (const float4*)(ps + tq2 * ZROW + ws * 32 + j0);
                const float4 q0 = p4[0], q1 = p4[1];
                rl[0] += q0.x; rl[1] += q0.y; rl[2] += q0.z; rl[3] += q0.w;
                rl[4] += q1.x; rl[5] += q1.y; rl[6] += q1.z; rl[7] += q1.w;
            }
            float4* ro = (float4*)(r2 + (sub * SUB + tq2) * TROW + j0);
            ro[0] = make_float4(rl[0]*rl[0], rl[1]*rl[1], rl[2]*rl[2], rl[3]*rl[3]);
            ro[1] = make_float4(rl[4]*rl[4], rl[5]*rl[5], rl[6]*rl[6], rl[7]*rl[7]);
        }
        __syncthreads();
    }

    // ---- phase3: thread = local t; all 32 j in registers ----
    const int lt = tid;
    float a[32];
    {
        const float4* rr = (const float4*)(r2 + lt * TROW);
#pragma unroll
        for (int i = 0; i < 8; ++i) {
            const float4 q4 = rr[i];
            a[4 * i] = q4.x; a[4 * i + 1] = q4.y;
            a[4 * i + 2] = q4.z; a[4 * i + 3] = q4.w;
        }
    }
    const float gu = __expf((float)lt * NLN_G);   // gamma^{-lt}
#pragma unroll
    for (int j = 0; j < 32; ++j) a[j] *= gu;

    // intra-warp inclusive prefix (per j)
#pragma unroll
    for (int j = 0; j < 32; ++j) {
        float v = a[j];
#pragma unroll
        for (int o = 1; o < 32; o <<= 1) {
            const float n = __shfl_up_sync(0xffffffffu, v, o);
            if (lane >= o) v += n;
        }
        a[j] = v;
    }
    if (lane == 31) {
        float4* wt = (float4*)(wtot + w * 32);
#pragma unroll
        for (int i = 0; i < 8; ++i)
            wt[i] = make_float4(a[4 * i], a[4 * i + 1], a[4 * i + 2], a[4 * i + 3]);
    }
    // decoupled lookback for previous chunk's h (c = slow grid index)
    if (c > 0 && tid == 0) {
        volatile int* f = (volatile int*)&g_flag[b * NCB + c - 1];
        while (*f == 0) { __nanosleep(40); }
    }
    __syncthreads();
    if (tid < 32)
        hps[tid] = (c > 0) ? g_hfull[(b * NCB + c - 1) * DOUT + tid] : 0.f;
    __syncthreads();

    // cross-warp prefix carry
#pragma unroll
    for (int wp = 0; wp < 3; ++wp) {
        if (w > wp) {
            const float4* wt = (const float4*)(wtot + wp * 32);
#pragma unroll
            for (int i = 0; i < 8; ++i) {
                const float4 q4 = wt[i];
                a[4 * i] += q4.x; a[4 * i + 1] += q4.y;
                a[4 * i + 2] += q4.z; a[4 * i + 3] += q4.w;
            }
        }
    }

    const float gl  = __expf(-(float)lt * NLN_G);   // gamma^{lt}
    const float gl1 = gl * GAMMA;                   // gamma^{lt+1}
    const int   tg  = t0 + lt;
    const float sden = (1.f - __expf(-(float)(tg + 1) * NLN_G)) * (1.f / (1.f - GAMMA));
    const float sinv = __fdividef(1.f, sden);

#pragma unroll
    for (int j = 0; j < 32; ++j)
        a[j] = fmaf(gl, a[j], gl1 * hps[j]);        // full h_t[j]

    if (tid == 127) {
        float4* hout = (float4*)&g_hfull[(b * NCB + c) * DOUT];
#pragma unroll
        for (int i = 0; i < 8; ++i)
            hout[i] = make_float4(a[4 * i], a[4 * i + 1], a[4 * i + 2], a[4 * i + 3]);
        __threadfence();
        atomicExch(&g_flag[b * NCB + c], 1);
    }

    // x = log(h/s + eps_h)
#pragma unroll
    for (int j = 0; j < 32; ++j)
        a[j] = __logf(fmaf(a[j], sinv, EPS_H));

    // LayerNorm (thread-local over 32 j)
    float mu = 0.f;
#pragma unroll
    for (int j = 0; j < 32; ++j) mu += a[j];
    mu *= (1.f / 32.f);
    float var = 0.f;
#pragma unroll
    for (int j = 0; j < 32; ++j) { const float dd = a[j] - mu; var = fmaf(dd, dd, var); }
    var *= (1.f / 32.f);
    const float rs = rsqrtf(var + LN_EPS);

    float l0 = 0.f, l1 = 0.f, l2 = 0.f, l3 = 0.f;
#pragma unroll
    for (int j = 0; j < 32; ++j) {
        const float xn = fmaf((a[j] - mu) * rs, lnw[j], lnb[j]);
        l0 = fmaf(xn, cw[j], l0);
        l1 = fmaf(xn, cw[32 + j], l1);
        l2 = fmaf(xn, cw[64 + j], l2);
        l3 = fmaf(xn, cw[96 + j], l3);
    }

    float4* xo = (float4*)(x_out + ((size_t)(b * T + tg)) * DOUT);
#pragma unroll
    for (int i = 0; i < 8; ++i)
        xo[i] = make_float4(a[4 * i], a[4 * i + 1], a[4 * i + 2], a[4 * i + 3]);
    float4* lo = (float4*)(logits_out + ((size_t)(b * T + tg)) * C);
    lo[0] = make_float4(l0 + cb[0], l1 + cb[1], l2 + cb[2], l3 + cb[3]);
}

// ---------------------------------------------------------------------------
extern "C" void kernel_launch(void* const* d_in, const int* in_sizes, int n_in,
                              void* d_out, int out_size)
{
    const float* z     = (const float*)d_in[0];
    const float* proj  = (const float*)d_in[1];
    const float* ln_w  = (const float*)d_in[2];
    const float* ln_b  = (const float*)d_in[3];
    const float* cls_w = (const float*)d_in[4];
    const float* cls_b = (const float*)d_in[5];

    float* out        = (float*)d_out;
    float* x_out      = out;
    float* logits_out = out + (size_t)B * T * DOUT;

    cudaFuncSetAttribute(k_fused, cudaFuncAttributeMaxDynamicSharedMemorySize,
                         SMEM_BYTES);

    k_stats<<<dim3(B, NCB), 128>>>(z);
    k_fused<<<dim3(B, NCB), 128, SMEM_BYTES>>>(z, proj, ln_w, ln_b, cls_w, cls_b,
                                               x_out, logits_out);
}

// round 13
// speedup vs baseline: 1.8193x; 1.0541x over previous
#include <cuda_runtime.h>
#include <cstdint>

namespace {
constexpr int B = 512, T = 512, D = 128, DOUT = 32, C = 4;
constexpr int NCB = 4;      // chunks over T
constexpr int CTB = 128;    // timesteps per block
constexpr int SUB = 32;     // timesteps per sub-tile
constexpr int NSUB = CTB / SUB;
constexpr float ALPHA  = 0.1f;
constexpr float GAMMA  = 0.9f;
constexpr float EPS    = 1e-5f;
constexpr float EPS_H  = 1e-6f;
constexpr float LN_EPS = 1e-5f;
constexpr float NLN_G  = 0.10536051565782628f;   // -ln(0.9)

constexpr int ZROW = 132;   // ps row pitch (floats)
constexpr int TROW = 36;    // zsT row pitch (floats)

// smem layout (floats) — r2 buffer moved to global
constexpr int OFF_PS   = 0;                    // [SUB][ZROW]: v-tile, then psum
constexpr int OFF_ZT   = OFF_PS + SUB * ZROW;  // [D][TROW]: delta2 -> z_tilde (transposed)
constexpr int OFF_P    = OFF_ZT + D * TROW;    // [D][DOUT]: proj
constexpr int OFF_VBAR = OFF_P + D * DOUT;     // [32]
constexpr int OFF_WTOT = OFF_VBAR + 32;        // [4][32]
constexpr int OFF_HP   = OFF_WTOT + 128;       // [32]
constexpr int OFF_LNW  = OFF_HP + 32;          // [32]
constexpr int OFF_LNB  = OFF_LNW + 32;         // [32]
constexpr int OFF_CW   = OFF_LNB + 32;         // [4][32]
constexpr int OFF_CB   = OFF_CW + 128;         // [4]
constexpr int OFF_IT   = OFF_CB + 4;           // [CTB] 1/tau
constexpr int OFF_IT1  = OFF_IT + CTB;         // [CTB] 1/max(tau-1,1)
constexpr int SMEM_FLOATS = OFF_IT1 + CTB;
constexpr int SMEM_BYTES  = SMEM_FLOATS * 4;   // ~54.3 KB -> 4 CTAs/SM
}

// scratch (static device globals — no allocation)
__device__ float g_s1[B * NCB * D];
__device__ float g_s2[B * NCB * D];
__device__ float g_r2[(size_t)B * T * DOUT];   // r^2 handoff (L2-resident, same kernel)
__device__ float g_hfull[B * NCB * DOUT];
__device__ int   g_flag[B * NCB];

__device__ __forceinline__ void fma2(unsigned long long& d,
                                     unsigned long long a,
                                     unsigned long long b,
                                     unsigned long long c)
{
    asm("fma.rn.f32x2 %0, %1, %2, %3;" : "=l"(d) : "l"(a), "l"(b), "l"(c));
}
__device__ __forceinline__ unsigned long long splat2(float a) {
    unsigned long long r;
    asm("mov.b64 %0, {%1, %1};" : "=l"(r) : "f"(a));
    return r;
}

// ---------------------------------------------------------------------------
// K1: per-(b,chunk) sums of z, z^2 (Welford carry) + flag reset
// ---------------------------------------------------------------------------
__global__ __launch_bounds__(128)
void k_stats(const float* __restrict__ z)
{
    const int b = blockIdx.x, c = blockIdx.y, d = threadIdx.x;
    const float* zp = z + ((size_t)(b * T + c * CTB)) * D + d;
    float s1a = 0.f, s2a = 0.f, s1b = 0.f, s2b = 0.f;
    float s1c = 0.f, s2c = 0.f, s1d = 0.f, s2d = 0.f;
#pragma unroll 2
    for (int t = 0; t < CTB; t += 4) {
        const float z0 = zp[(size_t)t * D];
        const float z1 = zp[(size_t)(t + 1) * D];
        const float z2 = zp[(size_t)(t + 2) * D];
        const float z3 = zp[(size_t)(t + 3) * D];
        s1a += z0; s2a = fmaf(z0, z0, s2a);
        s1b += z1; s2b = fmaf(z1, z1, s2b);
        s1c += z2; s2c = fmaf(z2, z2, s2c);
        s1d += z3; s2d = fmaf(z3, z3, s2d);
    }
    g_s1[(b * NCB + c) * D + d] = (s1a + s1b) + (s1c + s1d);
    g_s2[(b * NCB + c) * D + d] = (s2a + s2b) + (s2c + s2d);
    if (d == 0) g_flag[b * NCB + c] = 0;
}

// ---------------------------------------------------------------------------
// K2: fused normalize + project + h-prefix + tail; block per (b, 128-t chunk)
// ---------------------------------------------------------------------------
__global__ __launch_bounds__(128, 4)
void k_fused(const float* __restrict__ z, const float* __restrict__ proj,
             const float* __restrict__ ln_w, const float* __restrict__ ln_b,
             const float* __restrict__ cls_w, const float* __restrict__ cls_b,
             float* __restrict__ x_out, float* __restrict__ logits_out)
{
    const int b = blockIdx.x, c = blockIdx.y;
    const int tid = threadIdx.x, lane = tid & 31, w = tid >> 5;

    extern __shared__ float sm[];
    float* ps   = sm + OFF_PS;     // v-tile in phase1/1b/1c, psum in phase2
    float* zsT  = sm + OFF_ZT;     // [d][t], pitch TROW
    float* Psm  = sm + OFF_P;      // proj [d][j], pitch 32
    float* vbar = sm + OFF_VBAR;
    float* wtot = sm + OFF_WTOT;
    float* hps  = sm + OFF_HP;
    float* lnw  = sm + OFF_LNW;
    float* lnb  = sm + OFF_LNB;
    float* cw   = sm + OFF_CW;
    float* cb   = sm + OFF_CB;
    float* itab = sm + OFF_IT;
    float* itab1= sm + OFF_IT1;

    const int t0 = c * CTB;

    // ---- params + tables + proj into smem ----
#pragma unroll
    for (int i = 0; i < D * DOUT / 128; ++i)
        Psm[i * 128 + tid] = proj[i * 128 + tid];
    if (tid < 32) { lnw[tid] = ln_w[tid]; lnb[tid] = ln_b[tid]; }
    cw[tid] = cls_w[tid];
    if (tid < 4) cb[tid] = cls_b[tid];
    {
        const float tau = (float)(t0 + tid + 1);
        itab[tid]  = 1.0f / tau;
        itab1[tid] = 1.0f / fmaxf(tau - 1.f, 1.f);
    }

    // ---- Welford carry-in from chunk sums ----
    float s1 = 0.f, s2 = 0.f;
    for (int cp = 0; cp < c; ++cp) {
        s1 += g_s1[(b * NCB + cp) * D + tid];
        s2 += g_s2[(b * NCB + cp) * D + tid];
    }
    const float* zp = z + ((size_t)(b * T + t0)) * D + tid;

    const int tq2 = tid >> 2, jq2 = tid & 3;     // phase1b / 2b mapping
    const int jq = lane >> 3, tq = lane & 7;     // phase2 mapping
    __syncthreads();

    for (int sub = 0; sub < NSUB; ++sub) {
        // ---- phase1: Welford (thread = d) -> zsT[d][t] transposed, v -> ps ----
#pragma unroll 2
        for (int tg = 0; tg < SUB / 4; ++tg) {
            float4 d2q;
            float* d2a = (float*)&d2q;
#pragma unroll
            for (int i = 0; i < 4; ++i) {
                const int tl = tg * 4 + i;
                const int tb = sub * SUB + tl;
                const float zz = zp[(size_t)tb * D];
                s1 += zz;
                s2 = fmaf(zz, zz, s2);
                const float m = s1 * itab[tb];
                d2a[i] = zz - m;
                ps[tl * ZROW + tid] = fmaf(-s1, m, s2) * itab1[tb];
            }
            *(float4*)(zsT + tid * TROW + tg * 4) = d2q;
        }
        __syncthreads();

        // ---- phase1b: vbar per t (4 threads per t) ----
        {
            float p = 0.f;
            const float4* vr = (const float4*)(ps + tq2 * ZROW + jq2 * 32);
#pragma unroll
            for (int i = 0; i < 8; ++i) {
                const float4 q4 = vr[i];
                p += (q4.x + q4.y) + (q4.z + q4.w);
            }
            p += __shfl_xor_sync(0xffffffffu, p, 1);
            p += __shfl_xor_sync(0xffffffffu, p, 2);
            if (jq2 == 0) vbar[tq2] = p * (1.f / 128.f);
        }
        __syncthreads();

        // ---- phase1c: scale zsT row in place (thread = d) ----
#pragma unroll 2
        for (int i = 0; i < 8; ++i) {
            float4 q = *(const float4*)(zsT + tid * TROW + i * 4);
            float* qa = (float*)&q;
#pragma unroll
            for (int k = 0; k < 4; ++k) {
                const int tl = i * 4 + k;
                const float vt = fmaf(ALPHA, vbar[tl],
                                      (1.f - ALPHA) * ps[tl * ZROW + tid]);
                qa[k] *= rsqrtf(vt + EPS);
            }
            *(float4*)(zsT + tid * TROW + i * 4) = q;
        }
        __syncthreads();

        // ---- phase2: GEMM microkernel from smem ----
        // warp w: d in [32w,32w+32); thread (jq,tq): 8 j x 4 t tile.
        {
            unsigned long long acc[4][4];
#pragma unroll
            for (int i = 0; i < 4; ++i)
#pragma unroll
                for (int jj = 0; jj < 4; ++jj) acc[i][jj] = 0ull;

            const float* ztw = zsT + (w * 32) * TROW + tq * 4;
            const float* ppw = Psm + (w * 32) * DOUT + jq * 8;
#pragma unroll 4
            for (int d = 0; d < 32; ++d) {
                const float4 zq = *(const float4*)(ztw + d * TROW);
                const ulonglong2 pa = *(const ulonglong2*)(ppw + d * DOUT);
                const unsigned long long z0 = splat2(zq.x), z1 = splat2(zq.y);
                const unsigned long long z2 = splat2(zq.z), z3 = splat2(zq.w);
                fma2(acc[0][0], z0, pa.x, acc[0][0]);
                fma2(acc[0][1], z0, pa.y, acc[0][1]);
                fma2(acc[1][0], z1, pa.x, acc[1][0]);
                fma2(acc[1][1], z1, pa.y, acc[1][1]);
                fma2(acc[2][0], z2, pa.x, acc[2][0]);
                fma2(acc[2][1], z2, pa.y, acc[2][1]);
                fma2(acc[3][0], z3, pa.x, acc[3][0]);
                fma2(acc[3][1], z3, pa.y, acc[3][1]);
                const ulonglong2 pb = *(const ulonglong2*)(ppw + d * DOUT + 4);
                fma2(acc[0][2], z0, pb.x, acc[0][2]);
                fma2(acc[0][3], z0, pb.y, acc[0][3]);
                fma2(acc[1][2], z1, pb.x, acc[1][2]);
                fma2(acc[1][3], z1, pb.y, acc[1][3]);
                fma2(acc[2][2], z2, pb.x, acc[2][2]);
                fma2(acc[2][3], z2, pb.y, acc[2][3]);
                fma2(acc[3][2], z3, pb.x, acc[3][2]);
                fma2(acc[3][3], z3, pb.y, acc[3][3]);
            }
            // parity-ordered half stores: spread 16B positions -> 4 wf per STS.128
            const int par = tq & 1;
#pragma unroll
            for (int i = 0; i < 4; ++i) {
                ulonglong2* rowp = (ulonglong2*)(ps + (tq * 4 + i) * ZROW + w * 32 + jq * 8);
                const ulonglong2 lo = make_ulonglong2(acc[i][0], acc[i][1]);
                const ulonglong2 hi = make_ulonglong2(acc[i][2], acc[i][3]);
                rowp[par]     = par ? hi : lo;
                rowp[par ^ 1] = par ? lo : hi;
            }
        }
        __syncthreads();

        // ---- phase2b: reduce 4 warp partials -> r^2 -> global (L2) ----
        {
            const int j0 = jq2 * 8;
            float rl[8];
#pragma unroll
            for (int i = 0; i < 8; ++i) rl[i] = 0.f;
#pragma unroll
            for (int ws = 0; ws < 4; ++ws) {
                const float4* p4 = (const float4*)(ps + tq2 * ZROW + ws * 32 + j0);
                const float4 q0 = p4[0], q1 = p4[1];
                rl[0] += q0.x; rl[1] += q0.y; rl[2] += q0.z; rl[3] += q0.w;
                rl[4] += q1.x; rl[5] += q1.y; rl[6] += q1.z; rl[7] += q1.w;
            }
            float4* ro = (float4*)(g_r2 + ((size_t)(b * T + t0 + sub * SUB + tq2)) * DOUT + j0);
            ro[0] = make_float4(rl[0]*rl[0], rl[1]*rl[1], rl[2]*rl[2], rl[3]*rl[3]);
            ro[1] = make_float4(rl[4]*rl[4], rl[5]*rl[5], rl[6]*rl[6], rl[7]*rl[7]);
        }
        __syncthreads();
    }

    // ---- phase3: thread = local t; all 32 j in registers ----
    const int lt = tid;
    const int tg = t0 + lt;
    float a[32];
    {
        const float4* rr = (const float4*)(g_r2 + ((size_t)(b * T + tg)) * DOUT);
#pragma unroll
        for (int i = 0; i < 8; ++i) {
            const float4 q4 = rr[i];
            a[4 * i] = q4.x; a[4 * i + 1] = q4.y;
            a[4 * i + 2] = q4.z; a[4 * i + 3] = q4.w;
        }
    }
    const float gu = __expf((float)lt * NLN_G);   // gamma^{-lt}
#pragma unroll
    for (int j = 0; j < 32; ++j) a[j] *= gu;

    // intra-warp inclusive prefix (per j)
#pragma unroll
    for (int j = 0; j < 32; ++j) {
        float v = a[j];
#pragma unroll
        for (int o = 1; o < 32; o <<= 1) {
            const float n = __shfl_up_sync(0xffffffffu, v, o);
            if (lane >= o) v += n;
        }
        a[j] = v;
    }
    if (lane == 31) {
        float4* wt = (float4*)(wtot + w * 32);
#pragma unroll
        for (int i = 0; i < 8; ++i)
            wt[i] = make_float4(a[4 * i], a[4 * i + 1], a[4 * i + 2], a[4 * i + 3]);
    }
    // decoupled lookback for previous chunk's h (c = slow grid index)
    if (c > 0 && tid == 0) {
        volatile int* f = (volatile int*)&g_flag[b * NCB + c - 1];
        while (*f == 0) { __nanosleep(40); }
    }
    __syncthreads();
    if (tid < 32)
        hps[tid] = (c > 0) ? g_hfull[(b * NCB + c - 1) * DOUT + tid] : 0.f;
    __syncthreads();

    // cross-warp prefix carry
#pragma unroll
    for (int wp = 0; wp < 3; ++wp) {
        if (w > wp) {
            const float4* wt = (const float4*)(wtot + wp * 32);
#pragma unroll
            for (int i = 0; i < 8; ++i) {
                const float4 q4 = wt[i];
                a[4 * i] += q4.x; a[4 * i + 1] += q4.y;
                a[4 * i + 2] += q4.z; a[4 * i + 3] += q4.w;
            }
        }
    }

    const float gl  = __expf(-(float)lt * NLN_G);   // gamma^{lt}
    const float gl1 = gl * GAMMA;                   // gamma^{lt+1}
    const float sden = (1.f - __expf(-(float)(tg + 1) * NLN_G)) * (1.f / (1.f - GAMMA));
    const float sinv = __fdividef(1.f, sden);

#pragma unroll
    for (int j = 0; j < 32; ++j)
        a[j] = fmaf(gl, a[j], gl1 * hps[j]);        // full h_t[j]

    if (tid == 127) {
        float4* hout = (float4*)&g_hfull[(b * NCB + c) * DOUT];
#pragma unroll
        for (int i = 0; i < 8; ++i)
            hout[i] = make_float4(a[4 * i], a[4 * i + 1], a[4 * i + 2], a[4 * i + 3]);
        __threadfence();
        atomicExch(&g_flag[b * NCB + c], 1);
    }

    // x = log(h/s + eps_h)
#pragma unroll
    for (int j = 0; j < 32; ++j)
        a[j] = __logf(fmaf(a[j], sinv, EPS_H));

    // LayerNorm (thread-local over 32 j)
    float mu = 0.f;
#pragma unroll
    for (int j = 0; j < 32; ++j) mu += a[j];
    mu *= (1.f / 32.f);
    float var = 0.f;
#pragma unroll
    for (int j = 0; j < 32; ++j) { const float dd = a[j] - mu; var = fmaf(dd, dd, var); }
    var *= (1.f / 32.f);
    const float rs = rsqrtf(var + LN_EPS);

    float l0 = 0.f, l1 = 0.f, l2 = 0.f, l3 = 0.f;
#pragma unroll
    for (int j = 0; j < 32; ++j) {
        const float xn = fmaf((a[j] - mu) * rs, lnw[j], lnb[j]);
        l0 = fmaf(xn, cw[j], l0);
        l1 = fmaf(xn, cw[32 + j], l1);
        l2 = fmaf(xn, cw[64 + j], l2);
        l3 = fmaf(xn, cw[96 + j], l3);
    }

    float4* xo = (float4*)(x_out + ((size_t)(b * T + tg)) * DOUT);
#pragma unroll
    for (int i = 0; i < 8; ++i)
        xo[i] = make_float4(a[4 * i], a[4 * i + 1], a[4 * i + 2], a[4 * i + 3]);
    float4* lo = (float4*)(logits_out + ((size_t)(b * T + tg)) * C);
    lo[0] = make_float4(l0 + cb[0], l1 + cb[1], l2 + cb[2], l3 + cb[3]);
}

// ---------------------------------------------------------------------------
extern "C" void kernel_launch(void* const* d_in, const int* in_sizes, int n_in,
                              void* d_out, int out_size)
{
    const float* z     = (const float*)d_in[0];
    const float* proj  = (const float*)d_in[1];
    const float* ln_w  = (const float*)d_in[2];
    const float* ln_b  = (const float*)d_in[3];
    const float* cls_w = (const float*)d_in[4];
    const float* cls_b = (const float*)d_in[5];

    float* out        = (float*)d_out;
    float* x_out      = out;
    float* logits_out = out + (size_t)B * T * DOUT;

    cudaFuncSetAttribute(k_fused, cudaFuncAttributeMaxDynamicSharedMemorySize,
                         SMEM_BYTES);

    k_stats<<<dim3(B, NCB), 128>>>(z);
    k_fused<<<dim3(B, NCB), 128, SMEM_BYTES>>>(z, proj, ln_w, ln_b, cls_w, cls_b,
                                               x_out, logits_out);
}

// round 14
// speedup vs baseline: 1.9646x; 1.0799x over previous
#include <cuda_runtime.h>
#include <cstdint>

namespace {
constexpr int B = 512, T = 512, D = 128, DOUT = 32, C = 4;
constexpr int NCB = 4;      // chunks over T
constexpr int CTB = 128;    // timesteps per block
constexpr int SUB = 32;     // timesteps per sub-tile
constexpr int NSUB = CTB / SUB;
constexpr float ALPHA  = 0.1f;
constexpr float GAMMA  = 0.9f;
constexpr float EPS    = 1e-5f;
constexpr float EPS_H  = 1e-6f;
constexpr float LN_EPS = 1e-5f;
constexpr float NLN_G  = 0.10536051565782628f;   // -ln(0.9)

constexpr int ZROW = 132;   // ps row pitch (floats)
constexpr int TROW = 36;    // zsT row pitch (floats)

// smem layout (floats)
constexpr int OFF_PS   = 0;                    // [SUB][ZROW]: v-tile, then psum
constexpr int OFF_ZT   = OFF_PS + SUB * ZROW;  // [D][TROW]: z_tilde (transposed)
constexpr int OFF_P    = OFF_ZT + D * TROW;    // [D][DOUT]: proj
constexpr int OFF_VBAR = OFF_P + D * DOUT;     // [32]
constexpr int OFF_WTOT = OFF_VBAR + 32;        // [4][32]
constexpr int OFF_HP   = OFF_WTOT + 128;       // [32]
constexpr int OFF_LNW  = OFF_HP + 32;          // [32]
constexpr int OFF_LNB  = OFF_LNW + 32;         // [32]
constexpr int OFF_CW   = OFF_LNB + 32;         // [4][32]
constexpr int OFF_CB   = OFF_CW + 128;         // [4]
constexpr int OFF_IT   = OFF_CB + 4;           // [CTB] 1/tau
constexpr int OFF_IT1  = OFF_IT + CTB;         // [CTB] 1/max(tau-1,1)
constexpr int SMEM_FLOATS = OFF_IT1 + CTB;
constexpr int SMEM_BYTES  = SMEM_FLOATS * 4;   // ~54.3 KB -> 4 CTAs/SM
}

// scratch (static device globals — no allocation)
__device__ float g_s1[B * NCB * D];
__device__ float g_s2[B * NCB * D];
__device__ float g_r2[(size_t)B * T * DOUT];   // r^2 handoff (L2-resident)
__device__ float g_hfull[B * NCB * DOUT];
__device__ int   g_flag[B * NCB];

__device__ __forceinline__ void fma2(unsigned long long& d,
                                     unsigned long long a,
                                     unsigned long long b,
                                     unsigned long long c)
{
    asm("fma.rn.f32x2 %0, %1, %2, %3;" : "=l"(d) : "l"(a), "l"(b), "l"(c));
}
__device__ __forceinline__ unsigned long long splat2(float a) {
    unsigned long long r;
    asm("mov.b64 %0, {%1, %1};" : "=l"(r) : "f"(a));
    return r;
}

// ---------------------------------------------------------------------------
// K1: per-(b,chunk) sums of z, z^2 (Welford carry) + flag reset
// ---------------------------------------------------------------------------
__global__ __launch_bounds__(128)
void k_stats(const float* __restrict__ z)
{
    const int b = blockIdx.x, c = blockIdx.y, d = threadIdx.x;
    const float* zp = z + ((size_t)(b * T + c * CTB)) * D + d;
    float s1a = 0.f, s2a = 0.f, s1b = 0.f, s2b = 0.f;
    float s1c = 0.f, s2c = 0.f, s1d = 0.f, s2d = 0.f;
#pragma unroll 2
    for (int t = 0; t < CTB; t += 4) {
        const float z0 = zp[(size_t)t * D];
        const float z1 = zp[(size_t)(t + 1) * D];
        const float z2 = zp[(size_t)(t + 2) * D];
        const float z3 = zp[(size_t)(t + 3) * D];
        s1a += z0; s2a = fmaf(z0, z0, s2a);
        s1b += z1; s2b = fmaf(z1, z1, s2b);
        s1c += z2; s2c = fmaf(z2, z2, s2c);
        s1d += z3; s2d = fmaf(z3, z3, s2d);
    }
    g_s1[(b * NCB + c) * D + d] = (s1a + s1b) + (s1c + s1d);
    g_s2[(b * NCB + c) * D + d] = (s2a + s2b) + (s2c + s2d);
    if (d == 0) g_flag[b * NCB + c] = 0;
}

// ---------------------------------------------------------------------------
// K2: fused normalize + project + h-prefix + tail; block per (b, 128-t chunk)
// delta2/v carried in registers between phase1 and phase1c.
// ---------------------------------------------------------------------------
__global__ __launch_bounds__(128, 4)
void k_fused(const float* __restrict__ z, const float* __restrict__ proj,
             const float* __restrict__ ln_w, const float* __restrict__ ln_b,
             const float* __restrict__ cls_w, const float* __restrict__ cls_b,
             float* __restrict__ x_out, float* __restrict__ logits_out)
{
    const int b = blockIdx.x, c = blockIdx.y;
    const int tid = threadIdx.x, lane = tid & 31, w = tid >> 5;

    extern __shared__ float sm[];
    float* ps   = sm + OFF_PS;     // v-tile in phase1/1b, psum in phase2
    float* zsT  = sm + OFF_ZT;     // [d][t], pitch TROW
    float* Psm  = sm + OFF_P;      // proj [d][j], pitch 32
    float* vbar = sm + OFF_VBAR;
    float* wtot = sm + OFF_WTOT;
    float* hps  = sm + OFF_HP;
    float* lnw  = sm + OFF_LNW;
    float* lnb  = sm + OFF_LNB;
    float* cw   = sm + OFF_CW;
    float* cb   = sm + OFF_CB;
    float* itab = sm + OFF_IT;
    float* itab1= sm + OFF_IT1;

    const int t0 = c * CTB;

    // ---- params + tables + proj into smem ----
#pragma unroll
    for (int i = 0; i < D * DOUT / 128; ++i)
        Psm[i * 128 + tid] = proj[i * 128 + tid];
    if (tid < 32) { lnw[tid] = ln_w[tid]; lnb[tid] = ln_b[tid]; }
    cw[tid] = cls_w[tid];
    if (tid < 4) cb[tid] = cls_b[tid];
    {
        const float tau = (float)(t0 + tid + 1);
        itab[tid]  = 1.0f / tau;
        itab1[tid] = 1.0f / fmaxf(tau - 1.f, 1.f);
    }

    // ---- Welford carry-in from chunk sums ----
    float s1 = 0.f, s2 = 0.f;
    for (int cp = 0; cp < c; ++cp) {
        s1 += g_s1[(b * NCB + cp) * D + tid];
        s2 += g_s2[(b * NCB + cp) * D + tid];
    }
    const float* zp = z + ((size_t)(b * T + t0)) * D + tid;

    const int tq2 = tid >> 2, jq2 = tid & 3;     // phase1b / 2b mapping
    const int jq = lane >> 3, tq = lane & 7;     // phase2 mapping
    __syncthreads();

    for (int sub = 0; sub < NSUB; ++sub) {
        // ---- phase1: Welford (thread = d); delta2/v stay in REGISTERS ----
        float d2r[SUB], vr[SUB];
#pragma unroll
        for (int tl = 0; tl < SUB; ++tl) {
            const int tb = sub * SUB + tl;
            const float zz = zp[(size_t)tb * D];
            s1 += zz;
            s2 = fmaf(zz, zz, s2);
            const float m = s1 * itab[tb];
            d2r[tl] = zz - m;
            vr[tl]  = fmaf(-s1, m, s2) * itab1[tb];
            ps[tl * ZROW + tid] = vr[tl];
        }
        __syncthreads();

        // ---- phase1b: vbar per t (4 threads per t) ----
        {
            float p = 0.f;
            const float4* vrp = (const float4*)(ps + tq2 * ZROW + jq2 * 32);
#pragma unroll
            for (int i = 0; i < 8; ++i) {
                const float4 q4 = vrp[i];
                p += (q4.x + q4.y) + (q4.z + q4.w);
            }
            p += __shfl_xor_sync(0xffffffffu, p, 1);
            p += __shfl_xor_sync(0xffffffffu, p, 2);
            if (jq2 == 0) vbar[tq2] = p * (1.f / 128.f);
        }
        __syncthreads();

        // ---- phase1c: scale from registers -> zsT (store only) ----
#pragma unroll
        for (int i = 0; i < 8; ++i) {
            float4 q;
            float* qa = (float*)&q;
#pragma unroll
            for (int k = 0; k < 4; ++k) {
                const int tl = i * 4 + k;
                const float vt = fmaf(ALPHA, vbar[tl], (1.f - ALPHA) * vr[tl]);
                qa[k] = d2r[tl] * rsqrtf(vt + EPS);
            }
            *(float4*)(zsT + tid * TROW + i * 4) = q;
        }
        __syncthreads();

        // ---- phase2: GEMM microkernel from smem ----
        // warp w: d in [32w,32w+32); thread (jq,tq): 8 j x 4 t tile.
        {
            unsigned long long acc[4][4];
#pragma unroll
            for (int i = 0; i < 4; ++i)
#pragma unroll
                for (int jj = 0; jj < 4; ++jj) acc[i][jj] = 0ull;

            const float* ztw = zsT + (w * 32) * TROW + tq * 4;
            const float* ppw = Psm + (w * 32) * DOUT + jq * 8;
#pragma unroll 4
            for (int d = 0; d < 32; ++d) {
                const float4 zq = *(const float4*)(ztw + d * TROW);
                const ulonglong2 pa = *(const ulonglong2*)(ppw + d * DOUT);
                const unsigned long long z0 = splat2(zq.x), z1 = splat2(zq.y);
                const unsigned long long z2 = splat2(zq.z), z3 = splat2(zq.w);
                fma2(acc[0][0], z0, pa.x, acc[0][0]);
                fma2(acc[0][1], z0, pa.y, acc[0][1]);
                fma2(acc[1][0], z1, pa.x, acc[1][0]);
                fma2(acc[1][1], z1, pa.y, acc[1][1]);
                fma2(acc[2][0], z2, pa.x, acc[2][0]);
                fma2(acc[2][1], z2, pa.y, acc[2][1]);
                fma2(acc[3][0], z3, pa.x, acc[3][0]);
                fma2(acc[3][1], z3, pa.y, acc[3][1]);
                const ulonglong2 pb = *(const ulonglong2*)(ppw + d * DOUT + 4);
                fma2(acc[0][2], z0, pb.x, acc[0][2]);
                fma2(acc[0][3], z0, pb.y, acc[0][3]);
                fma2(acc[1][2], z1, pb.x, acc[1][2]);
                fma2(acc[1][3], z1, pb.y, acc[1][3]);
                fma2(acc[2][2], z2, pb.x, acc[2][2]);
                fma2(acc[2][3], z2, pb.y, acc[2][3]);
                fma2(acc[3][2], z3, pb.x, acc[3][2]);
                fma2(acc[3][3], z3, pb.y, acc[3][3]);
            }
            // parity-ordered half stores
            const int par = tq & 1;
#pragma unroll
            for (int i = 0; i < 4; ++i) {
                ulonglong2* rowp = (ulonglong2*)(ps + (tq * 4 + i) * ZROW + w * 32 + jq * 8);
                const ulonglong2 lo = make_ulonglong2(acc[i][0], acc[i][1]);
                const ulonglong2 hi = make_ulonglong2(acc[i][2], acc[i][3]);
                rowp[par]     = par ? hi : lo;
                rowp[par ^ 1] = par ? lo : hi;
            }
        }
        __syncthreads();

        // ---- phase2b: reduce 4 warp partials -> r^2 -> global (L2) ----
        {
            const int j0 = jq2 * 8;
            float rl[8];
#pragma unroll
            for (int i = 0; i < 8; ++i) rl[i] = 0.f;
#pragma unroll
            for (int ws = 0; ws < 4; ++ws) {
                const float4* p4 = (const float4*)(ps + tq2 * ZROW + ws * 32 + j0);
                const float4 q0 = p4[0], q1 = p4[1];
                rl[0] += q0.x; rl[1] += q0.y; rl[2] += q0.z; rl[3] += q0.w;
                rl[4] += q1.x; rl[5] += q1.y; rl[6] += q1.z; rl[7] += q1.w;
            }
            float4* ro = (float4*)(g_r2 + ((size_t)(b * T + t0 + sub * SUB + tq2)) * DOUT + j0);
            ro[0] = make_float4(rl[0]*rl[0], rl[1]*rl[1], rl[2]*rl[2], rl[3]*rl[3]);
            ro[1] = make_float4(rl[4]*rl[4], rl[5]*rl[5], rl[6]*rl[6], rl[7]*rl[7]);
        }
        __syncthreads();
    }

    // ---- phase3: thread = local t; all 32 j in registers ----
    const int lt = tid;
    const int tg = t0 + lt;
    float a[32];
    {
        const float4* rr = (const float4*)(g_r2 + ((size_t)(b * T + tg)) * DOUT);
#pragma unroll
        for (int i = 0; i < 8; ++i) {
            const float4 q4 = rr[i];
            a[4 * i] = q4.x; a[4 * i + 1] = q4.y;
            a[4 * i + 2] = q4.z; a[4 * i + 3] = q4.w;
        }
    }
    const float gu = __expf((float)lt * NLN_G);   // gamma^{-lt}
#pragma unroll
    for (int j = 0; j < 32; ++j) a[j] *= gu;

    // intra-warp inclusive prefix (per j)
#pragma unroll
    for (int j = 0; j < 32; ++j) {
        float v = a[j];
#pragma unroll
        for (int o = 1; o < 32; o <<= 1) {
            const float n = __shfl_up_sync(0xffffffffu, v, o);
            if (lane >= o) v += n;
        }
        a[j] = v;
    }
    if (lane == 31) {
        float4* wt = (float4*)(wtot + w * 32);
#pragma unroll
        for (int i = 0; i < 8; ++i)
            wt[i] = make_float4(a[4 * i], a[4 * i + 1], a[4 * i + 2], a[4 * i + 3]);
    }
    // decoupled lookback for previous chunk's h (c = slow grid index)
    if (c > 0 && tid == 0) {
        volatile int* f = (volatile int*)&g_flag[b * NCB + c - 1];
        while (*f == 0) { __nanosleep(40); }
    }
    __syncthreads();
    if (tid < 32)
        hps[tid] = (c > 0) ? g_hfull[(b * NCB + c - 1) * DOUT + tid] : 0.f;
    __syncthreads();

    // cross-warp prefix carry
#pragma unroll
    for (int wp = 0; wp < 3; ++wp) {
        if (w > wp) {
            const float4* wt = (const float4*)(wtot + wp * 32);
#pragma unroll
            for (int i = 0; i < 8; ++i) {
                const float4 q4 = wt[i];
                a[4 * i] += q4.x; a[4 * i + 1] += q4.y;
                a[4 * i + 2] += q4.z; a[4 * i + 3] += q4.w;
            }
        }
    }

    const float gl  = __expf(-(float)lt * NLN_G);   // gamma^{lt}
    const float gl1 = gl * GAMMA;                   // gamma^{lt+1}
    const float sden = (1.f - __expf(-(float)(tg + 1) * NLN_G)) * (1.f / (1.f - GAMMA));
    const float sinv = __fdividef(1.f, sden);

#pragma unroll
    for (int j = 0; j < 32; ++j)
        a[j] = fmaf(gl, a[j], gl1 * hps[j]);        // full h_t[j]

    if (tid == 127) {
        float4* hout = (float4*)&g_hfull[(b * NCB + c) * DOUT];
#pragma unroll
        for (int i = 0; i < 8; ++i)
            hout[i] = make_float4(a[4 * i], a[4 * i + 1], a[4 * i + 2], a[4 * i + 3]);
        __threadfence();
        atomicExch(&g_flag[b * NCB + c], 1);
    }

    // x = log(h/s + eps_h)
#pragma unroll
    for (int j = 0; j < 32; ++j)
        a[j] = __logf(fmaf(a[j], sinv, EPS_H));

    // LayerNorm (thread-local over 32 j)
    float mu = 0.f;
#pragma unroll
    for (int j = 0; j < 32; ++j) mu += a[j];
    mu *= (1.f / 32.f);
    float var = 0.f;
#pragma unroll
    for (int j = 0; j < 32; ++j) { const float dd = a[j] - mu; var = fmaf(dd, dd, var); }
    var *= (1.f / 32.f);
    const float rs = rsqrtf(var + LN_EPS);

    float l0 = 0.f, l1 = 0.f, l2 = 0.f, l3 = 0.f;
#pragma unroll
    for (int j = 0; j < 32; ++j) {
        const float xn = fmaf((a[j] - mu) * rs, lnw[j], lnb[j]);
        l0 = fmaf(xn, cw[j], l0);
        l1 = fmaf(xn, cw[32 + j], l1);
        l2 = fmaf(xn, cw[64 + j], l2);
        l3 = fmaf(xn, cw[96 + j], l3);
    }

    float4* xo = (float4*)(x_out + ((size_t)(b * T + tg)) * DOUT);
#pragma unroll
    for (int i = 0; i < 8; ++i)
        xo[i] = make_float4(a[4 * i], a[4 * i + 1], a[4 * i + 2], a[4 * i + 3]);
    float4* lo = (float4*)(logits_out + ((size_t)(b * T + tg)) * C);
    lo[0] = make_float4(l0 + cb[0], l1 + cb[1], l2 + cb[2], l3 + cb[3]);
}

// ---------------------------------------------------------------------------
extern "C" void kernel_launch(void* const* d_in, const int* in_sizes, int n_in,
                              void* d_out, int out_size)
{
    const float* z     = (const float*)d_in[0];
    const float* proj  = (const float*)d_in[1];
    const float* ln_w  = (const float*)d_in[2];
    const float* ln_b  = (const float*)d_in[3];
    const float* cls_w = (const float*)d_in[4];
    const float* cls_b = (const float*)d_in[5];

    float* out        = (float*)d_out;
    float* x_out      = out;
    float* logits_out = out + (size_t)B * T * DOUT;

    cudaFuncSetAttribute(k_fused, cudaFuncAttributeMaxDynamicSharedMemorySize,
                         SMEM_BYTES);

    k_stats<<<dim3(B, NCB), 128>>>(z);
    k_fused<<<dim3(B, NCB), 128, SMEM_BYTES>>>(z, proj, ln_w, ln_b, cls_w, cls_b,
                                               x_out, logits_out);
}